// round 2
// baseline (speedup 1.0000x reference)
#include <cuda_runtime.h>

typedef unsigned long long u64;

// ---------------- packed f32x2 helpers (Blackwell FFMA2) ----------------
__device__ __forceinline__ u64 pack2(float a, float b) {
    u64 r; asm("mov.b64 %0, {%1, %2};" : "=l"(r) : "f"(a), "f"(b)); return r;
}
__device__ __forceinline__ u64 pack1(float a) { return pack2(a, a); }
__device__ __forceinline__ void unpack2(u64 v, float& a, float& b) {
    asm("mov.b64 {%0, %1}, %2;" : "=f"(a), "=f"(b) : "l"(v));
}
__device__ __forceinline__ u64 fma2(u64 a, u64 b, u64 c) {
    u64 d; asm("fma.rn.f32x2 %0, %1, %2, %3;" : "=l"(d) : "l"(a), "l"(b), "l"(c));
    return d;
}
__device__ __forceinline__ u64 relu2(u64 v) {
    float a, b; unpack2(v, a, b);
    a = fmaxf(a, 0.0f); b = fmaxf(b, 0.0f);
    return pack2(a, b);
}

// ---------------- constants ----------------
#define NTHREADS 256
#define ROWS_PER_THREAD 4
#define PAIRS 2
static constexpr int BATCH = 2097152;
static constexpr int CHUNK = BATCH / ROWS_PER_THREAD;  // 524288

// fused layer0+1 weights: W01[5][8] then b01[5]
__device__ float g_fused[45];

// ---------------- prep: fuse layer0 (no relu) into layer1 ----------------
// relu(W1 (W0 x + b0) + b1) = relu((W1 W0) x + (W1 b0 + b1))
__global__ void prep_kernel(const float* __restrict__ W0, const float* __restrict__ b0,
                            const float* __restrict__ W1, const float* __restrict__ b1) {
    int t = threadIdx.x;
    if (t < 40) {
        int o = t >> 3, k = t & 7;
        float s = 0.0f;
#pragma unroll
        for (int h = 0; h < 5; h++) s += W1[o * 5 + h] * W0[h * 8 + k];
        g_fused[t] = s;
    } else if (t < 45) {
        int o = t - 40;
        float s = b1[o];
#pragma unroll
        for (int h = 0; h < 5; h++) s += W1[o * 5 + h] * b0[h];
        g_fused[40 + o] = s;
    }
}

// shared weight layout offsets (indices into u64 array)
#define OFF_FW   0    // 45: W01(40) + b01(5)
#define OFF_W2   45   // 25
#define OFF_B2   70   // 5
#define OFF_W3   75   // 25
#define OFF_B3   100  // 5
#define OFF_W4   105  // 25
#define OFF_B4   130  // 5
#define OFF_W5   135  // 20
#define OFF_B5   155  // 4
#define W_TOTAL  159

__device__ __forceinline__ void hidden_stage(u64 a[PAIRS][5], const u64* sw, int woff, int boff) {
#pragma unroll
    for (int p = 0; p < PAIRS; p++) {
        u64 h[5];
#pragma unroll
        for (int o = 0; o < 5; o++) {
            u64 acc = sw[boff + o];
#pragma unroll
            for (int k = 0; k < 5; k++) acc = fma2(a[p][k], sw[woff + o * 5 + k], acc);
            h[o] = relu2(acc);
        }
#pragma unroll
        for (int o = 0; o < 5; o++) a[p][o] = h[o];
    }
}

__global__ __launch_bounds__(NTHREADS, 4) void mlp_kernel(
    const float4* __restrict__ x,
    const float* __restrict__ W2, const float* __restrict__ b2,
    const float* __restrict__ W3, const float* __restrict__ b3,
    const float* __restrict__ W4, const float* __restrict__ b4,
    const float* __restrict__ W5, const float* __restrict__ b5,
    float4* __restrict__ out) {
    // weights pre-packed as duplicated-halves u64 so fma.rn.f32x2 operands
    // can be rematerialized from shared instead of living in registers
    __shared__ u64 sw[W_TOTAL];
    const int t = threadIdx.x;

    if (t < W_TOTAL) {
        float v;
        if (t < 45)        v = g_fused[t];
        else if (t < 70)   v = W2[t - OFF_W2];
        else if (t < 75)   v = b2[t - OFF_B2];
        else if (t < 100)  v = W3[t - OFF_W3];
        else if (t < 105)  v = b3[t - OFF_B3];
        else if (t < 130)  v = W4[t - OFF_W4];
        else if (t < 135)  v = b4[t - OFF_B4];
        else if (t < 155)  v = W5[t - OFF_W5];
        else               v = b5[t - OFF_B5];
        sw[t] = pack1(v);
    }
    __syncthreads();

    const int idx = blockIdx.x * NTHREADS + t;  // 0..CHUNK-1

    u64 a[PAIRS][5];

    // ---- stage 1: fused layer01 (8 -> relu(5)) ----
#pragma unroll
    for (int p = 0; p < PAIRS; p++) {
        const int r0 = idx + (2 * p) * CHUNK;
        const int r1 = idx + (2 * p + 1) * CHUNK;
        float4 xa0 = __ldg(&x[2 * r0]);
        float4 xa1 = __ldg(&x[2 * r0 + 1]);
        float4 xb0 = __ldg(&x[2 * r1]);
        float4 xb1 = __ldg(&x[2 * r1 + 1]);
        u64 xv[8];
        xv[0] = pack2(xa0.x, xb0.x); xv[1] = pack2(xa0.y, xb0.y);
        xv[2] = pack2(xa0.z, xb0.z); xv[3] = pack2(xa0.w, xb0.w);
        xv[4] = pack2(xa1.x, xb1.x); xv[5] = pack2(xa1.y, xb1.y);
        xv[6] = pack2(xa1.z, xb1.z); xv[7] = pack2(xa1.w, xb1.w);
#pragma unroll
        for (int o = 0; o < 5; o++) {
            u64 acc = sw[OFF_FW + 40 + o];
#pragma unroll
            for (int k = 0; k < 8; k++) acc = fma2(xv[k], sw[OFF_FW + o * 8 + k], acc);
            a[p][o] = relu2(acc);
        }
    }

    // ---- stages 2..4: hidden layers (5 -> relu(5)) ----
    hidden_stage(a, sw, OFF_W2, OFF_B2);
    hidden_stage(a, sw, OFF_W3, OFF_B3);
    hidden_stage(a, sw, OFF_W4, OFF_B4);

    // ---- stage 5: output layer (5 -> relu(4)) + store ----
#pragma unroll
    for (int p = 0; p < PAIRS; p++) {
        float lo[4], hi[4];
#pragma unroll
        for (int o = 0; o < 4; o++) {
            u64 acc = sw[OFF_B5 + o];
#pragma unroll
            for (int k = 0; k < 5; k++) acc = fma2(a[p][k], sw[OFF_W5 + o * 5 + k], acc);
            acc = relu2(acc);
            unpack2(acc, lo[o], hi[o]);
        }
        const int r0 = idx + (2 * p) * CHUNK;
        const int r1 = idx + (2 * p + 1) * CHUNK;
        out[r0] = make_float4(lo[0], lo[1], lo[2], lo[3]);
        out[r1] = make_float4(hi[0], hi[1], hi[2], hi[3]);
    }
}

extern "C" void kernel_launch(void* const* d_in, const int* in_sizes, int n_in,
                              void* d_out, int out_size) {
    const float* x  = (const float*)d_in[0];
    const float* W0 = (const float*)d_in[1];
    const float* b0 = (const float*)d_in[2];
    const float* W1 = (const float*)d_in[3];
    const float* b1 = (const float*)d_in[4];
    const float* W2 = (const float*)d_in[5];
    const float* b2 = (const float*)d_in[6];
    const float* W3 = (const float*)d_in[7];
    const float* b3 = (const float*)d_in[8];
    const float* W4 = (const float*)d_in[9];
    const float* b4 = (const float*)d_in[10];
    const float* W5 = (const float*)d_in[11];
    const float* b5 = (const float*)d_in[12];

    prep_kernel<<<1, 64>>>(W0, b0, W1, b1);

    const int grid = (BATCH / ROWS_PER_THREAD) / NTHREADS;  // 2048
    mlp_kernel<<<grid, NTHREADS>>>((const float4*)x,
                                   W2, b2, W3, b3, W4, b4, W5, b5,
                                   (float4*)d_out);
}

// round 3
// speedup vs baseline: 1.3236x; 1.3236x over previous
#include <cuda_runtime.h>

typedef unsigned long long u64;

// ---------------- packed f32x2 helpers (Blackwell FFMA2) ----------------
__device__ __forceinline__ u64 pack2(float a, float b) {
    u64 r; asm("mov.b64 %0, {%1, %2};" : "=l"(r) : "f"(a), "f"(b)); return r;
}
__device__ __forceinline__ u64 pack1(float a) { return pack2(a, a); }
__device__ __forceinline__ void unpack2(u64 v, float& a, float& b) {
    asm("mov.b64 {%0, %1}, %2;" : "=f"(a), "=f"(b) : "l"(v));
}
__device__ __forceinline__ u64 fma2(u64 a, u64 b, u64 c) {
    u64 d; asm("fma.rn.f32x2 %0, %1, %2, %3;" : "=l"(d) : "l"(a), "l"(b), "l"(c));
    return d;
}
__device__ __forceinline__ u64 relu2(u64 v) {
    float a, b; unpack2(v, a, b);
    a = fmaxf(a, 0.0f); b = fmaxf(b, 0.0f);
    return pack2(a, b);
}

// ---------------- constants ----------------
#define NTHREADS 256
#define ROWS_PER_THREAD 4
#define PAIRS 2
static constexpr int BATCH = 2097152;
static constexpr int CHUNK = BATCH / ROWS_PER_THREAD;  // 524288

// ---------------- padded weight table layout (u64/float indices) ----------
// Rows start 16B-aligned (even u64 index) so ulonglong2 LDS.128 works.
#define OFF_FW   0    // W01 fused: 5 rows x 8 (stride 8)          [0,40)
#define OFF_FB   40   // b01: 5                                    [40,45) pad->48
#define OFF_W2   48   // 5 rows stride 6 (5 w + 1 pad)             [48,78)
#define OFF_B2   78   // 5                                         [78,83) pad->84
#define OFF_W3   84   //                                           [84,114)
#define OFF_B3   114  //                                           [114,119) pad->120
#define OFF_W4   120  //                                           [120,150)
#define OFF_B4   150  //                                           [150,155) pad->156
#define OFF_W5   156  // 4 rows stride 6                           [156,180)
#define OFF_B5   180  // 4                                         [180,184)
#define W_TOTAL  184

__device__ float g_w[W_TOTAL];

// ---------------- prep: fuse layer0 (no relu) into layer1, build table ----
// relu(W1 (W0 x + b0) + b1) = relu((W1 W0) x + (W1 b0 + b1))
__global__ void prep_kernel(const float* __restrict__ W0, const float* __restrict__ b0,
                            const float* __restrict__ W1, const float* __restrict__ b1,
                            const float* __restrict__ W2, const float* __restrict__ b2,
                            const float* __restrict__ W3, const float* __restrict__ b3,
                            const float* __restrict__ W4, const float* __restrict__ b4,
                            const float* __restrict__ W5, const float* __restrict__ b5) {
    int t = threadIdx.x;
    if (t >= W_TOTAL) return;
    float v = 0.0f;
    if (t < 40) {
        int o = t >> 3, k = t & 7;
        float s = 0.0f;
#pragma unroll
        for (int h = 0; h < 5; h++) s += W1[o * 5 + h] * W0[h * 8 + k];
        v = s;
    } else if (t < 45) {
        int o = t - 40;
        float s = b1[o];
#pragma unroll
        for (int h = 0; h < 5; h++) s += W1[o * 5 + h] * b0[h];
        v = s;
    } else if (t < 48) {
        v = 0.0f;
    } else if (t < 78) {
        int i = t - OFF_W2, o = i / 6, k = i % 6;
        v = (k < 5) ? W2[o * 5 + k] : 0.0f;
    } else if (t < 84) {
        v = (t < 83) ? b2[t - OFF_B2] : 0.0f;
    } else if (t < 114) {
        int i = t - OFF_W3, o = i / 6, k = i % 6;
        v = (k < 5) ? W3[o * 5 + k] : 0.0f;
    } else if (t < 120) {
        v = (t < 119) ? b3[t - OFF_B3] : 0.0f;
    } else if (t < 150) {
        int i = t - OFF_W4, o = i / 6, k = i % 6;
        v = (k < 5) ? W4[o * 5 + k] : 0.0f;
    } else if (t < 156) {
        v = (t < 155) ? b4[t - OFF_B4] : 0.0f;
    } else if (t < 180) {
        int i = t - OFF_W5, o = i / 6, k = i % 6;
        v = (k < 5) ? W5[o * 5 + k] : 0.0f;
    } else {
        v = b5[t - OFF_B5];
    }
    g_w[t] = v;
}

// one hidden stage (5 -> relu(5)): weight row loaded once via LDS.128,
// applied to both pairs (p-inner) so each LDS feeds 2 fma2
__device__ __forceinline__ void hidden_stage(u64 a[PAIRS][5], const u64* sw, int woff, int boff) {
    u64 h[PAIRS][5];
#pragma unroll
    for (int o = 0; o < 5; o++) {
        ulonglong2 wa = *reinterpret_cast<const ulonglong2*>(sw + woff + o * 6);
        ulonglong2 wb = *reinterpret_cast<const ulonglong2*>(sw + woff + o * 6 + 2);
        u64 w4 = sw[woff + o * 6 + 4];
        u64 bb = sw[boff + o];
#pragma unroll
        for (int p = 0; p < PAIRS; p++) {
            u64 acc = bb;
            acc = fma2(a[p][0], wa.x, acc);
            acc = fma2(a[p][1], wa.y, acc);
            acc = fma2(a[p][2], wb.x, acc);
            acc = fma2(a[p][3], wb.y, acc);
            acc = fma2(a[p][4], w4, acc);
            h[p][o] = relu2(acc);
        }
    }
#pragma unroll
    for (int p = 0; p < PAIRS; p++)
#pragma unroll
        for (int o = 0; o < 5; o++) a[p][o] = h[p][o];
}

__global__ __launch_bounds__(NTHREADS, 4) void mlp_kernel(
    const float4* __restrict__ x, float4* __restrict__ out) {
    __shared__ __align__(16) u64 sw[W_TOTAL];
    const int t = threadIdx.x;
    if (t < W_TOTAL) sw[t] = pack1(g_w[t]);
    __syncthreads();

    const int idx = blockIdx.x * NTHREADS + t;  // 0..CHUNK-1

    // front-batch all 8 input vectors (rows r = idx + r*CHUNK, r=0..3; 2 float4 each)
    float4 xr0[ROWS_PER_THREAD], xr1[ROWS_PER_THREAD];
#pragma unroll
    for (int r = 0; r < ROWS_PER_THREAD; r++) {
        const long long row = idx + (long long)r * CHUNK;
        xr0[r] = __ldg(&x[2 * row]);
        xr1[r] = __ldg(&x[2 * row + 1]);
    }

    // ---- stage 1: fused layer01 (8 -> relu(5)), bias-init accumulate ----
    u64 a[PAIRS][5];
#pragma unroll
    for (int o = 0; o < 5; o++) {
        u64 bb = sw[OFF_FB + o];
#pragma unroll
        for (int p = 0; p < PAIRS; p++) a[p][o] = bb;
    }
#pragma unroll
    for (int o = 0; o < 5; o++) {
        ulonglong2 wa = *reinterpret_cast<const ulonglong2*>(sw + OFF_FW + o * 8);
        ulonglong2 wb = *reinterpret_cast<const ulonglong2*>(sw + OFF_FW + o * 8 + 2);
        ulonglong2 wc = *reinterpret_cast<const ulonglong2*>(sw + OFF_FW + o * 8 + 4);
        ulonglong2 wd = *reinterpret_cast<const ulonglong2*>(sw + OFF_FW + o * 8 + 6);
#pragma unroll
        for (int p = 0; p < PAIRS; p++) {
            const int ra = 2 * p, rb = 2 * p + 1;
            u64 acc = a[p][o];
            acc = fma2(pack2(xr0[ra].x, xr0[rb].x), wa.x, acc);
            acc = fma2(pack2(xr0[ra].y, xr0[rb].y), wa.y, acc);
            acc = fma2(pack2(xr0[ra].z, xr0[rb].z), wb.x, acc);
            acc = fma2(pack2(xr0[ra].w, xr0[rb].w), wb.y, acc);
            acc = fma2(pack2(xr1[ra].x, xr1[rb].x), wc.x, acc);
            acc = fma2(pack2(xr1[ra].y, xr1[rb].y), wc.y, acc);
            acc = fma2(pack2(xr1[ra].z, xr1[rb].z), wd.x, acc);
            acc = fma2(pack2(xr1[ra].w, xr1[rb].w), wd.y, acc);
            a[p][o] = acc;
        }
    }
#pragma unroll
    for (int p = 0; p < PAIRS; p++)
#pragma unroll
        for (int o = 0; o < 5; o++) a[p][o] = relu2(a[p][o]);

    // ---- stages 2..4: hidden layers ----
    hidden_stage(a, sw, OFF_W2, OFF_B2);
    hidden_stage(a, sw, OFF_W3, OFF_B3);
    hidden_stage(a, sw, OFF_W4, OFF_B4);

    // ---- stage 5: output layer (5 -> relu(4)) + store ----
    float res[ROWS_PER_THREAD][4];
#pragma unroll
    for (int o = 0; o < 4; o++) {
        ulonglong2 wa = *reinterpret_cast<const ulonglong2*>(sw + OFF_W5 + o * 6);
        ulonglong2 wb = *reinterpret_cast<const ulonglong2*>(sw + OFF_W5 + o * 6 + 2);
        u64 w4 = sw[OFF_W5 + o * 6 + 4];
        u64 bb = sw[OFF_B5 + o];
#pragma unroll
        for (int p = 0; p < PAIRS; p++) {
            u64 acc = bb;
            acc = fma2(a[p][0], wa.x, acc);
            acc = fma2(a[p][1], wa.y, acc);
            acc = fma2(a[p][2], wb.x, acc);
            acc = fma2(a[p][3], wb.y, acc);
            acc = fma2(a[p][4], w4, acc);
            acc = relu2(acc);
            unpack2(acc, res[2 * p][o], res[2 * p + 1][o]);
        }
    }
#pragma unroll
    for (int r = 0; r < ROWS_PER_THREAD; r++) {
        const long long row = idx + (long long)r * CHUNK;
        out[row] = make_float4(res[r][0], res[r][1], res[r][2], res[r][3]);
    }
}

extern "C" void kernel_launch(void* const* d_in, const int* in_sizes, int n_in,
                              void* d_out, int out_size) {
    const float* x  = (const float*)d_in[0];
    const float* W0 = (const float*)d_in[1];
    const float* b0 = (const float*)d_in[2];
    const float* W1 = (const float*)d_in[3];
    const float* b1 = (const float*)d_in[4];
    const float* W2 = (const float*)d_in[5];
    const float* b2 = (const float*)d_in[6];
    const float* W3 = (const float*)d_in[7];
    const float* b3 = (const float*)d_in[8];
    const float* W4 = (const float*)d_in[9];
    const float* b4 = (const float*)d_in[10];
    const float* W5 = (const float*)d_in[11];
    const float* b5 = (const float*)d_in[12];

    prep_kernel<<<1, NTHREADS>>>(W0, b0, W1, b1, W2, b2, W3, b3, W4, b4, W5, b5);

    const int grid = (BATCH / ROWS_PER_THREAD) / NTHREADS;  // 2048
    mlp_kernel<<<grid, NTHREADS>>>((const float4*)x, (float4*)d_out);
}

// round 4
// speedup vs baseline: 1.3997x; 1.0575x over previous
#include <cuda_runtime.h>

typedef unsigned long long u64;

// ---------------- packed f32x2 helpers (Blackwell FFMA2) ----------------
__device__ __forceinline__ u64 pack2(float a, float b) {
    u64 r; asm("mov.b64 %0, {%1, %2};" : "=l"(r) : "f"(a), "f"(b)); return r;
}
__device__ __forceinline__ u64 pack1(float a) { return pack2(a, a); }
__device__ __forceinline__ void unpack2(u64 v, float& a, float& b) {
    asm("mov.b64 {%0, %1}, %2;" : "=f"(a), "=f"(b) : "l"(v));
}
__device__ __forceinline__ u64 fma2(u64 a, u64 b, u64 c) {
    u64 d; asm("fma.rn.f32x2 %0, %1, %2, %3;" : "=l"(d) : "l"(a), "l"(b), "l"(c));
    return d;
}
__device__ __forceinline__ u64 relu2(u64 v) {
    float a, b; unpack2(v, a, b);
    a = fmaxf(a, 0.0f); b = fmaxf(b, 0.0f);
    return pack2(a, b);
}

// ---------------- constants ----------------
#define NTHREADS 128
#define ROWS_PER_THREAD 4
#define PAIRS 2
static constexpr int BATCH = 2097152;
static constexpr int CHUNK = BATCH / ROWS_PER_THREAD;  // 524288

// ---------------- padded weight table (u64 indices), bias embedded -------
// stage1 fused: 5 rows, stride 10: [w0..w7, b, pad]       [0,50)
// W2..W4:       5 rows, stride 6:  [w0..w4, b]            [50,80) [80,110) [110,140)
// W5:           4 rows, stride 6:  [w0..w4, b]            [140,164)
#define OFF_FW   0
#define OFF_W2   50
#define OFF_W3   80
#define OFF_W4   110
#define OFF_W5   140
#define W_TOTAL  164

// compute fused/padded table entry t directly from raw weights
__device__ __forceinline__ float table_entry(
    int t,
    const float* __restrict__ W0, const float* __restrict__ b0,
    const float* __restrict__ W1, const float* __restrict__ b1,
    const float* __restrict__ W2, const float* __restrict__ b2,
    const float* __restrict__ W3, const float* __restrict__ b3,
    const float* __restrict__ W4, const float* __restrict__ b4,
    const float* __restrict__ W5, const float* __restrict__ b5) {
    if (t < 50) {
        int o = t / 10, k = t % 10;
        if (k < 8) {
            // fused W01[o][k] = sum_h W1[o][h] * W0[h][k]
            float s = 0.0f;
#pragma unroll
            for (int h = 0; h < 5; h++) s += W1[o * 5 + h] * W0[h * 8 + k];
            return s;
        } else if (k == 8) {
            // fused b01[o] = b1[o] + sum_h W1[o][h] * b0[h]
            float s = b1[o];
#pragma unroll
            for (int h = 0; h < 5; h++) s += W1[o * 5 + h] * b0[h];
            return s;
        }
        return 0.0f;
    } else if (t < 80) {
        int i = t - OFF_W2, o = i / 6, k = i % 6;
        return (k < 5) ? W2[o * 5 + k] : b2[o];
    } else if (t < 110) {
        int i = t - OFF_W3, o = i / 6, k = i % 6;
        return (k < 5) ? W3[o * 5 + k] : b3[o];
    } else if (t < 140) {
        int i = t - OFF_W4, o = i / 6, k = i % 6;
        return (k < 5) ? W4[o * 5 + k] : b4[o];
    } else {
        int i = t - OFF_W5, o = i / 6, k = i % 6;
        return (k < 5) ? W5[o * 5 + k] : b5[o];
    }
}

// one hidden stage (5 -> relu(5)): 3x LDS.128 per neuron row (weights+bias),
// each row applied to both pairs
__device__ __forceinline__ void hidden_stage(u64 a[PAIRS][5], const u64* sw, int woff) {
    u64 h[PAIRS][5];
#pragma unroll
    for (int o = 0; o < 5; o++) {
        ulonglong2 wa = *reinterpret_cast<const ulonglong2*>(sw + woff + o * 6);
        ulonglong2 wb = *reinterpret_cast<const ulonglong2*>(sw + woff + o * 6 + 2);
        ulonglong2 wc = *reinterpret_cast<const ulonglong2*>(sw + woff + o * 6 + 4);
#pragma unroll
        for (int p = 0; p < PAIRS; p++) {
            u64 acc = wc.y;  // bias
            acc = fma2(a[p][0], wa.x, acc);
            acc = fma2(a[p][1], wa.y, acc);
            acc = fma2(a[p][2], wb.x, acc);
            acc = fma2(a[p][3], wb.y, acc);
            acc = fma2(a[p][4], wc.x, acc);
            h[p][o] = relu2(acc);
        }
    }
#pragma unroll
    for (int p = 0; p < PAIRS; p++)
#pragma unroll
        for (int o = 0; o < 5; o++) a[p][o] = h[p][o];
}

__global__ __launch_bounds__(NTHREADS, 8) void mlp_kernel(
    const float4* __restrict__ x, float4* __restrict__ out,
    const float* __restrict__ W0, const float* __restrict__ b0,
    const float* __restrict__ W1, const float* __restrict__ b1,
    const float* __restrict__ W2, const float* __restrict__ b2,
    const float* __restrict__ W3, const float* __restrict__ b3,
    const float* __restrict__ W4, const float* __restrict__ b4,
    const float* __restrict__ W5, const float* __restrict__ b5) {
    __shared__ __align__(16) u64 sw[W_TOTAL];
    const int t = threadIdx.x;
    const int idx = blockIdx.x * NTHREADS + t;  // 0..CHUNK-1

    // front-batch input loads (independent of the weight table)
    float4 xr0[ROWS_PER_THREAD], xr1[ROWS_PER_THREAD];
#pragma unroll
    for (int r = 0; r < ROWS_PER_THREAD; r++) {
        const long long row = idx + (long long)r * CHUNK;
        xr0[r] = __ldg(&x[2 * row]);
        xr1[r] = __ldg(&x[2 * row + 1]);
    }

    // in-block weight prep: fuse layer0 into layer1, build padded packed table
    {
        int i0 = t, i1 = t + NTHREADS;
        float v0 = table_entry(i0, W0, b0, W1, b1, W2, b2, W3, b3, W4, b4, W5, b5);
        sw[i0] = pack1(v0);
        if (i1 < W_TOTAL) {
            float v1 = table_entry(i1, W0, b0, W1, b1, W2, b2, W3, b3, W4, b4, W5, b5);
            sw[i1] = pack1(v1);
        }
    }
    __syncthreads();

    // ---- stage 1: fused layer01 (8 -> relu(5)) ----
    u64 a[PAIRS][5];
#pragma unroll
    for (int o = 0; o < 5; o++) {
        ulonglong2 wa = *reinterpret_cast<const ulonglong2*>(sw + OFF_FW + o * 10);
        ulonglong2 wb = *reinterpret_cast<const ulonglong2*>(sw + OFF_FW + o * 10 + 2);
        ulonglong2 wc = *reinterpret_cast<const ulonglong2*>(sw + OFF_FW + o * 10 + 4);
        ulonglong2 wd = *reinterpret_cast<const ulonglong2*>(sw + OFF_FW + o * 10 + 6);
        ulonglong2 we = *reinterpret_cast<const ulonglong2*>(sw + OFF_FW + o * 10 + 8);
#pragma unroll
        for (int p = 0; p < PAIRS; p++) {
            const int ra = 2 * p, rb = 2 * p + 1;
            u64 acc = we.x;  // bias
            acc = fma2(pack2(xr0[ra].x, xr0[rb].x), wa.x, acc);
            acc = fma2(pack2(xr0[ra].y, xr0[rb].y), wa.y, acc);
            acc = fma2(pack2(xr0[ra].z, xr0[rb].z), wb.x, acc);
            acc = fma2(pack2(xr0[ra].w, xr0[rb].w), wb.y, acc);
            acc = fma2(pack2(xr1[ra].x, xr1[rb].x), wc.x, acc);
            acc = fma2(pack2(xr1[ra].y, xr1[rb].y), wc.y, acc);
            acc = fma2(pack2(xr1[ra].z, xr1[rb].z), wd.x, acc);
            acc = fma2(pack2(xr1[ra].w, xr1[rb].w), wd.y, acc);
            a[p][o] = relu2(acc);
        }
    }

    // ---- stages 2..4: hidden layers ----
    hidden_stage(a, sw, OFF_W2);
    hidden_stage(a, sw, OFF_W3);
    hidden_stage(a, sw, OFF_W4);

    // ---- stage 5: output layer (5 -> relu(4)) + streaming store ----
    float res[ROWS_PER_THREAD][4];
#pragma unroll
    for (int o = 0; o < 4; o++) {
        ulonglong2 wa = *reinterpret_cast<const ulonglong2*>(sw + OFF_W5 + o * 6);
        ulonglong2 wb = *reinterpret_cast<const ulonglong2*>(sw + OFF_W5 + o * 6 + 2);
        ulonglong2 wc = *reinterpret_cast<const ulonglong2*>(sw + OFF_W5 + o * 6 + 4);
#pragma unroll
        for (int p = 0; p < PAIRS; p++) {
            u64 acc = wc.y;  // bias
            acc = fma2(a[p][0], wa.x, acc);
            acc = fma2(a[p][1], wa.y, acc);
            acc = fma2(a[p][2], wb.x, acc);
            acc = fma2(a[p][3], wb.y, acc);
            acc = fma2(a[p][4], wc.x, acc);
            acc = relu2(acc);
            unpack2(acc, res[2 * p][o], res[2 * p + 1][o]);
        }
    }
#pragma unroll
    for (int r = 0; r < ROWS_PER_THREAD; r++) {
        const long long row = idx + (long long)r * CHUNK;
        __stcs(&out[row], make_float4(res[r][0], res[r][1], res[r][2], res[r][3]));
    }
}

extern "C" void kernel_launch(void* const* d_in, const int* in_sizes, int n_in,
                              void* d_out, int out_size) {
    const float* x  = (const float*)d_in[0];
    const float* W0 = (const float*)d_in[1];
    const float* b0 = (const float*)d_in[2];
    const float* W1 = (const float*)d_in[3];
    const float* b1 = (const float*)d_in[4];
    const float* W2 = (const float*)d_in[5];
    const float* b2 = (const float*)d_in[6];
    const float* W3 = (const float*)d_in[7];
    const float* b3 = (const float*)d_in[8];
    const float* W4 = (const float*)d_in[9];
    const float* b4 = (const float*)d_in[10];
    const float* W5 = (const float*)d_in[11];
    const float* b5 = (const float*)d_in[12];

    const int grid = (BATCH / ROWS_PER_THREAD) / NTHREADS;  // 4096
    mlp_kernel<<<grid, NTHREADS>>>((const float4*)x, (float4*)d_out,
                                   W0, b0, W1, b1, W2, b2, W3, b3, W4, b4, W5, b5);
}